// round 15
// baseline (speedup 1.0000x reference)
#include <cuda_runtime.h>
#include <math.h>

#define CH   64
#define HH   256
#define WW   256
#define HWX  65536
#define NPIX (2*HWX)
#define TBL  256          // PE table resolution per axis (rows = TBL+1)

typedef unsigned long long u64t;

__device__ __forceinline__ u64t pk2(float lo, float hi) {
    u64t r; asm("mov.b64 %0,{%1,%2};" : "=l"(r) : "f"(lo), "f"(hi)); return r;
}
__device__ __forceinline__ void upk2(float& lo, float& hi, u64t v) {
    asm("mov.b64 {%0,%1},%2;" : "=f"(lo), "=f"(hi) : "l"(v));
}
__device__ __forceinline__ u64t ffma2(u64t a, u64t b, u64t c) {
    u64t d; asm("fma.rn.f32x2 %0,%1,%2,%3;" : "=l"(d) : "l"(a), "l"(b), "l"(c)); return d;
}
__device__ __forceinline__ u64t fmul2(u64t a, u64t b) {
    u64t d; asm("mul.rn.f32x2 %0,%1,%2;" : "=l"(d) : "l"(a), "l"(b)); return d;
}

// Precomputed-constant buffer layout (floats) in d_const
#define OFF_QWS  0
#define OFF_KWS  4096
#define OFF_VWS  8192
#define OFF_QWPE 12288
#define OFF_KB   20480
#define OFF_VB   20736
#define OFF_QB   20992
#define OFF_FREQ 21056
#define NCONST   21088

__device__ float d_const[NCONST];
__device__ u64t  q_scr2[32 * NPIX];          // packed q scratch, [i][pix]
__device__ float pe_tab[2 * (TBL+1) * 64];   // PE lerp tables
__device__ float suppT[64 * NPIX];           // pixel-major support [b*HWX+hw][c]

// AV smem layout (floats):
#define SM_WBUF 0          // 4096  (kws, later vws)
#define SM_KB   4096       // 256
#define SM_VB   4352       // 256
#define SM_OFF  4608       // 512 ints (4 warps x 128)
#define SM_F    5120       // 4 warps x 128 rows x 17 floats = 8704
#define SM_N    (5120 + 4*128*17)   // 13824 floats = 55296 B

// ---------------------------------------------------------------------------
__global__ void iw_setup_kernel(const float* __restrict__ qw, const float* __restrict__ qb,
                                const float* __restrict__ kw, const float* __restrict__ kb,
                                const float* __restrict__ vw, const float* __restrict__ vb)
{
    const int g = blockIdx.x * 256 + threadIdx.x;
    const float LN1E4_32 = 9.210340371976184f / 32.0f;

    if (g < 4096) {
        int c = g >> 6, o = g & 63;
        d_const[OFF_QWS + g] = qw[o*128 + 2*c] + qw[o*128 + 2*c + 1];
        d_const[OFF_KWS + g] = kw[o*128 + 2*c] + kw[o*128 + 2*c + 1];
        d_const[OFF_VWS + g] = vw[o*128 + 2*c] + vw[o*128 + 2*c + 1];
    }
    {
        int j = g >> 8, r = g & 255, t4 = r >> 6, o = r & 63;
        int col = (t4 < 2) ? (2*j + t4) : (64 + 2*j + (t4 - 2));
        d_const[OFF_QWPE + g] = qw[o*128 + col];
    }
    if (g < 32) d_const[OFF_FREQ + g] = __expf(-(float)g * LN1E4_32);
    if (g < 64) d_const[OFF_QB + g]   = qb[g];

    const float SW = (float)(2.0 * M_PI / (1.0 + 1e-6));
    int W = g >> 5, j = g & 31;
    int uv = W >> 6, o = W & 63;
    float uu = (float)(uv >> 1), vv = (float)(uv & 1);
    float f = __expf(-(float)j * LN1E4_32);
    float syv, cyv, sxv, cxv;
    __sincosf(uu * SW * f, &syv, &cyv);
    __sincosf(vv * SW * f, &sxv, &cxv);
    float aK = syv*kw[o*128+2*j] + cyv*kw[o*128+2*j+1]
             + sxv*kw[o*128+64+2*j] + cxv*kw[o*128+64+2*j+1];
    float aV = syv*vw[o*128+2*j] + cyv*vw[o*128+2*j+1]
             + sxv*vw[o*128+64+2*j] + cxv*vw[o*128+64+2*j+1];
    #pragma unroll
    for (int s = 16; s > 0; s >>= 1) {
        aK += __shfl_xor_sync(0xffffffffu, aK, s);
        aV += __shfl_xor_sync(0xffffffffu, aV, s);
    }
    if (j == 0) {
        d_const[OFF_KB + W] = aK + kb[o];
        d_const[OFF_VB + W] = aV + vb[o];
    }
}

// ---------------------------------------------------------------------------
__global__ void __launch_bounds__(64) iw_tab_kernel()
{
    __shared__ float sy[32], cy[32];
    int blk  = blockIdx.x;
    int axis = blk / (TBL+1);
    int t    = blk % (TBL+1);
    int tid  = threadIdx.x;

    const float PE2 = (float)(2.0 * M_PI / (2.0 + 1e-6));
    if (tid < 32) {
        float f = d_const[OFF_FREQ + tid];
        __sincosf(((float)t / (float)TBL) * PE2 * f, &sy[tid], &cy[tid]);
    }
    __syncthreads();

    float acc = 0.f;
    #pragma unroll 4
    for (int j = 0; j < 32; j++) {
        acc = fmaf(sy[j], d_const[OFF_QWPE + j*256 + axis*128 + tid],      acc);
        acc = fmaf(cy[j], d_const[OFF_QWPE + j*256 + axis*128 + 64 + tid], acc);
    }
    pe_tab[(axis*(TBL+1) + t)*64 + tid] = acc;
}

// ---------------------------------------------------------------------------
// Transpose: supp [c][hw] -> suppT [hw][c] (256B pixel rows).
// ---------------------------------------------------------------------------
__global__ void __launch_bounds__(256) iw_transpose_kernel(const float* __restrict__ supp)
{
    __shared__ float t[64][65];
    int tile = blockIdx.x;                  // 2048 tiles of 64 pixels
    int gpx0 = tile * 64;
    int b    = gpx0 >> 16;
    int px0  = gpx0 & 65535;

    const float* s = supp + b*(CH*HWX) + px0;
    int lx = threadIdx.x & 63;
    int ly = threadIdx.x >> 6;
    #pragma unroll
    for (int c = 0; c < 64; c += 4)
        t[c + ly][lx] = s[(c + ly)*HWX + lx];
    __syncthreads();

    float* d = suppT + (size_t)gpx0 * 64;
    int cx = threadIdx.x & 63;
    int py = threadIdx.x >> 6;
    #pragma unroll
    for (int p = 0; p < 64; p += 4)
        d[(p + py)*64 + cx] = t[cx][p + py];
}

// ---------------------------------------------------------------------------
// Q kernel (unchanged from R13 best)
// ---------------------------------------------------------------------------
__global__ void __launch_bounds__(128, 5) iw_q_kernel(
    const float* __restrict__ curr, const float* __restrict__ flow)
{
    __shared__ float sm[4160];
    for (int i = threadIdx.x; i < 4096; i += 128) sm[i] = d_const[OFF_QWS + i];
    if (threadIdx.x < 64) sm[4096 + threadIdx.x] = d_const[OFF_QB + threadIdx.x];
    __syncthreads();

    const float* s_qws = sm;

    int pix = blockIdx.x * 128 + threadIdx.x;
    int b   = pix >> 16;
    int rem = pix & 65535;
    int yy  = rem >> 8;
    int xx  = rem & 255;

    float2 fl = reinterpret_cast<const float2*>(flow)[pix];
    float gy = (float)yy + fl.y;
    float gx = (float)xx + fl.x;
    float dy = gy - floorf(gy);
    float dx = gx - floorf(gx);

    const float* currB = curr + b*(CH*HWX) + yy*WW + xx;

    u64t q2[32];
    const u64t* qb2 = reinterpret_cast<const u64t*>(sm + 4096);
    #pragma unroll
    for (int i = 0; i < 32; i++) q2[i] = qb2[i];

    #pragma unroll
    for (int axis = 0; axis < 2; axis++) {
        float d  = axis ? dx : dy;
        float td = d * (float)TBL;
        int   it = (int)td;
        float ft = td - (float)it;
        u64t ft2 = pk2(ft, ft), om2 = pk2(1.f - ft, 1.f - ft);
        const ulonglong2* g0 = reinterpret_cast<const ulonglong2*>(
            pe_tab + (axis*(TBL+1) + it)*64);
        #pragma unroll
        for (int i = 0; i < 16; i++) {
            ulonglong2 a = __ldg(g0 + i);
            ulonglong2 c = __ldg(g0 + 16 + i);
            u64t v0 = ffma2(om2, a.x, q2[2*i]);
            u64t v1 = ffma2(om2, a.y, q2[2*i+1]);
            q2[2*i]   = ffma2(ft2, c.x, v0);
            q2[2*i+1] = ffma2(ft2, c.y, v1);
        }
    }

    for (int cb = 0; cb < 64; cb += 16) {
        float fc[16];
        #pragma unroll
        for (int k = 0; k < 16; k++) fc[k] = __ldg(currB + (cb + k)*HWX);
        #pragma unroll
        for (int k = 0; k < 16; k++) {
            u64t fc2 = pk2(fc[k], fc[k]);
            const ulonglong2* wc4 = reinterpret_cast<const ulonglong2*>(s_qws + (cb + k)*64);
            #pragma unroll
            for (int i = 0; i < 16; i++) {
                ulonglong2 w = wc4[i];
                q2[2*i]   = ffma2(fc2, w.x, q2[2*i]);
                q2[2*i+1] = ffma2(fc2, w.y, q2[2*i+1]);
            }
        }
    }

    const float SC = 0.35355339059327376f;
    u64t sc2 = pk2(SC, SC);
    #pragma unroll
    for (int i = 0; i < 32; i++)
        q_scr2[i*NPIX + pix] = fmul2(q2[i], sc2);
}

// ---------------------------------------------------------------------------
// AV kernel: warp-cooperative gather staging through smem.
// Warp owns 32 pixels; per 16-ch chunk, 16 sliced LDG.128 stage all 4 window
// rows into a 17-float-stride smem buffer; lanes then read conflict-free.
// Weights two-phased in smem (kws -> vws). (128,3).
// ---------------------------------------------------------------------------
__global__ void __launch_bounds__(128, 3) iw_av_kernel(
    const float* __restrict__ flow, float* __restrict__ out)
{
    extern __shared__ float sm[];
    float* s_wbuf = sm + SM_WBUF;
    float* s_kb   = sm + SM_KB;
    float* s_vb   = sm + SM_VB;
    int*   s_off  = (int*)(sm + SM_OFF);

    int tid  = threadIdx.x;
    int wid  = tid >> 5;
    int lane = tid & 31;
    float* s_F = sm + SM_F + wid*(128*17);
    int*   w_off = s_off + wid*128;

    // phase-1 weights: kws + biases
    for (int i = tid; i < 4096; i += 128) s_wbuf[i] = d_const[OFF_KWS + i];
    for (int i = tid; i < 256;  i += 128) {
        s_kb[i] = d_const[OFF_KB + i];
        s_vb[i] = d_const[OFF_VB + i];
    }

    int pix = blockIdx.x * 128 + tid;
    int b   = pix >> 16;
    int rem = pix & 65535;
    int yy  = rem >> 8;
    int xx  = rem & 255;

    float2 fl = reinterpret_cast<const float2*>(flow)[pix];
    float gy = (float)yy + fl.y;
    float gx = (float)xx + fl.x;
    int iy = (int)floorf(gy), ix = (int)floorf(gx);
    int r0 = min(max(iy,     0), HH-1);
    int r1 = min(max(iy + 1, 0), HH-1);
    int c0 = min(max(ix,     0), WW-1);
    int c1 = min(max(ix + 1, 0), WW-1);
    int base = b*HWX;
    w_off[0*32 + lane] = base + r0*WW + c0;
    w_off[1*32 + lane] = base + r0*WW + c1;
    w_off[2*32 + lane] = base + r1*WW + c0;
    w_off[3*32 + lane] = base + r1*WW + c1;
    __syncthreads();

    // q packed, pre-scaled by SC
    u64t q2[32];
    #pragma unroll
    for (int i = 0; i < 32; i++) q2[i] = q_scr2[i*NPIX + pix];

    // attn init: bias-dot
    u64t A01[8], A23[8];
    #pragma unroll
    for (int h = 0; h < 8; h++) {
        float av[4];
        #pragma unroll
        for (int u = 0; u < 4; u++) {
            const ulonglong2* kb4 = reinterpret_cast<const ulonglong2*>(s_kb + u*64);
            ulonglong2 wa = kb4[h*2], wb = kb4[h*2 + 1];
            u64t d2 = fmul2(q2[h*4], wa.x);
            d2 = ffma2(q2[h*4+1], wa.y, d2);
            d2 = ffma2(q2[h*4+2], wb.x, d2);
            d2 = ffma2(q2[h*4+3], wb.y, d2);
            float lo, hi; upk2(lo, hi, d2);
            av[u] = lo + hi;
        }
        A01[h] = pk2(av[0], av[1]);
        A23[h] = pk2(av[2], av[3]);
    }

    // -------- attn pass: 4 chunks of 16 channels --------
    for (int cb = 0; cb < 4; cb++) {
        __syncwarp();
        // cooperative stage: 16 LDG.128, each covering 8 (px,pos) 64B units
        #pragma unroll
        for (int i = 0; i < 16; i++) {
            int u   = i*8 + (lane >> 2);
            int seg = lane & 3;
            int ro  = w_off[u];
            float4 v = __ldg(reinterpret_cast<const float4*>(
                suppT + (size_t)ro*64 + cb*16 + seg*4));
            float* dst = s_F + u*17 + seg*4;
            dst[0] = v.x; dst[1] = v.y; dst[2] = v.z; dst[3] = v.w;
        }
        __syncwarp();

        #pragma unroll
        for (int cc = 0; cc < 16; cc++) {
            float f00 = s_F[(0*32 + lane)*17 + cc];
            float f01 = s_F[(1*32 + lane)*17 + cc];
            float f10 = s_F[(2*32 + lane)*17 + cc];
            float f11 = s_F[(3*32 + lane)*17 + cc];
            const ulonglong2* wc4 = reinterpret_cast<const ulonglong2*>(
                s_wbuf + (cb*16 + cc)*64);
            u64t F01 = pk2(f00, f01);
            u64t F23 = pk2(f10, f11);
            #pragma unroll
            for (int h = 0; h < 8; h++) {
                ulonglong2 wa = wc4[h*2], wb = wc4[h*2 + 1];
                u64t d2 = fmul2(q2[h*4], wa.x);
                d2 = ffma2(q2[h*4+1], wa.y, d2);
                d2 = ffma2(q2[h*4+2], wb.x, d2);
                d2 = ffma2(q2[h*4+3], wb.y, d2);
                float lo, hi; upk2(lo, hi, d2);
                float qk = lo + hi;
                u64t qk2 = pk2(qk, qk);
                A01[h] = ffma2(qk2, F01, A01[h]);
                A23[h] = ffma2(qk2, F23, A23[h]);
            }
        }
    }

    // -------- softmax (SC pre-folded) --------
    #pragma unroll
    for (int h = 0; h < 8; h++) {
        float a0, a1, a2, a3;
        upk2(a0, a1, A01[h]);
        upk2(a2, a3, A23[h]);
        float m = fmaxf(fmaxf(a0, a1), fmaxf(a2, a3));
        float p0 = __expf(a0 - m);
        float p1 = __expf(a1 - m);
        float p2 = __expf(a2 - m);
        float p3 = __expf(a3 - m);
        float inv = __fdividef(1.0f, p0 + p1 + p2 + p3);
        A01[h] = pk2(p0*inv, p1*inv);
        A23[h] = pk2(p2*inv, p3*inv);
    }

    // -------- phase-2 weights: vws --------
    __syncthreads();
    for (int i = tid; i < 4096; i += 128) s_wbuf[i] = d_const[OFF_VWS + i];
    __syncthreads();

    // -------- value pass: re-stage chunks (L1-hot), fold --------
    u64t out2[32];
    #pragma unroll
    for (int i = 0; i < 32; i++) out2[i] = 0ULL;

    for (int cb = 0; cb < 4; cb++) {
        __syncwarp();
        #pragma unroll
        for (int i = 0; i < 16; i++) {
            int u   = i*8 + (lane >> 2);
            int seg = lane & 3;
            int ro  = w_off[u];
            float4 v = __ldg(reinterpret_cast<const float4*>(
                suppT + (size_t)ro*64 + cb*16 + seg*4));
            float* dst = s_F + u*17 + seg*4;
            dst[0] = v.x; dst[1] = v.y; dst[2] = v.z; dst[3] = v.w;
        }
        __syncwarp();

        #pragma unroll
        for (int cc = 0; cc < 16; cc++) {
            float f00 = s_F[(0*32 + lane)*17 + cc];
            float f01 = s_F[(1*32 + lane)*17 + cc];
            float f10 = s_F[(2*32 + lane)*17 + cc];
            float f11 = s_F[(3*32 + lane)*17 + cc];
            const ulonglong2* wc4 = reinterpret_cast<const ulonglong2*>(
                s_wbuf + (cb*16 + cc)*64);
            u64t F01 = pk2(f00, f01);
            u64t F23 = pk2(f10, f11);
            u64t gv2[8];
            #pragma unroll
            for (int h = 0; h < 8; h++) {
                u64t g2 = fmul2(A01[h], F01);
                g2 = ffma2(A23[h], F23, g2);
                float lo, hi; upk2(lo, hi, g2);
                float gv = lo + hi;
                gv2[h] = pk2(gv, gv);
            }
            #pragma unroll
            for (int i = 0; i < 16; i++) {
                ulonglong2 w = wc4[i];
                out2[2*i]   = ffma2(gv2[i >> 1], w.x, out2[2*i]);
                out2[2*i+1] = ffma2(gv2[i >> 1], w.y, out2[2*i+1]);
            }
        }
    }

    // v pe-bias term (packed) + store
    const u64t* vb2 = reinterpret_cast<const u64t*>(s_vb);
    #pragma unroll
    for (int h = 0; h < 8; h++) {
        float a0, a1, a2, a3;
        upk2(a0, a1, A01[h]);
        upk2(a2, a3, A23[h]);
        u64t b0 = pk2(a0, a0), b1 = pk2(a1, a1);
        u64t b2 = pk2(a2, a2), b3 = pk2(a3, a3);
        #pragma unroll
        for (int k = 0; k < 4; k++) {
            int i = h*4 + k;
            u64t acc = out2[i];
            acc = ffma2(b0, vb2[0*32 + i], acc);
            acc = ffma2(b1, vb2[1*32 + i], acc);
            acc = ffma2(b2, vb2[2*32 + i], acc);
            acc = ffma2(b3, vb2[3*32 + i], acc);
            out2[i] = acc;
        }
    }

    float* outB = out + b*(CH*HWX) + yy*WW + xx;
    #pragma unroll
    for (int i = 0; i < 32; i++) {
        float lo, hi; upk2(lo, hi, out2[i]);
        outB[(2*i)*HWX]     = lo;
        outB[(2*i + 1)*HWX] = hi;
    }
}

// ---------------------------------------------------------------------------
extern "C" void kernel_launch(void* const* d_in, const int* in_sizes, int n_in,
                              void* d_out, int out_size)
{
    const float* supp = (const float*)d_in[0];
    const float* flow = (const float*)d_in[1];
    const float* curr = (const float*)d_in[2];
    const float* qw   = (const float*)d_in[3];
    const float* qb   = (const float*)d_in[4];
    const float* kw   = (const float*)d_in[5];
    const float* kb   = (const float*)d_in[6];
    const float* vw   = (const float*)d_in[7];
    const float* vb   = (const float*)d_in[8];
    float* outp = (float*)d_out;

    cudaFuncSetAttribute(iw_av_kernel,
                         cudaFuncAttributeMaxDynamicSharedMemorySize, SM_N * 4);

    iw_setup_kernel<<<32, 256>>>(qw, qb, kw, kb, vw, vb);
    iw_tab_kernel<<<2*(TBL+1), 64>>>();
    iw_transpose_kernel<<<NPIX / 64, 256>>>(supp);
    iw_q_kernel<<<NPIX / 128, 128>>>(curr, flow);
    iw_av_kernel<<<NPIX / 128, 128, SM_N * 4>>>(flow, outp);
}

// round 16
// speedup vs baseline: 1.3852x; 1.3852x over previous
#include <cuda_runtime.h>
#include <math.h>

#define CH   64
#define HH   256
#define WW   256
#define HWX  65536
#define NPIX (2*HWX)
#define TBL  256          // PE table resolution per axis (rows = TBL+1)

typedef unsigned long long u64t;

__device__ __forceinline__ u64t pk2(float lo, float hi) {
    u64t r; asm("mov.b64 %0,{%1,%2};" : "=l"(r) : "f"(lo), "f"(hi)); return r;
}
__device__ __forceinline__ void upk2(float& lo, float& hi, u64t v) {
    asm("mov.b64 {%0,%1},%2;" : "=f"(lo), "=f"(hi) : "l"(v));
}
__device__ __forceinline__ u64t ffma2(u64t a, u64t b, u64t c) {
    u64t d; asm("fma.rn.f32x2 %0,%1,%2,%3;" : "=l"(d) : "l"(a), "l"(b), "l"(c)); return d;
}
__device__ __forceinline__ u64t fmul2(u64t a, u64t b) {
    u64t d; asm("mul.rn.f32x2 %0,%1,%2;" : "=l"(d) : "l"(a), "l"(b)); return d;
}

// Precomputed-constant buffer layout (floats) in d_const
#define OFF_QWS  0
#define OFF_KWS  4096
#define OFF_VWS  8192
#define OFF_QWPE 12288
#define OFF_KB   20480
#define OFF_VB   20736
#define OFF_QB   20992
#define OFF_FREQ 21056
#define NCONST   21088

__device__ float d_const[NCONST];
__device__ float pe_tab[2 * (TBL+1) * 64];   // PE lerp tables: [axis][t][o]

// Fused-kernel smem layout (floats)
#define FS_QWS  0
#define FS_KWS  4096
#define FS_VWS  8192
#define FS_KB   12288
#define FS_VB   12544
#define FS_QB   12800
#define FS_N    12864      // 51456 B

// ---------------------------------------------------------------------------
// Setup kernel: fold weights, window-PE biases (warp per entry), freqs.
// ---------------------------------------------------------------------------
__global__ void iw_setup_kernel(const float* __restrict__ qw, const float* __restrict__ qb,
                                const float* __restrict__ kw, const float* __restrict__ kb,
                                const float* __restrict__ vw, const float* __restrict__ vb)
{
    const int g = blockIdx.x * 256 + threadIdx.x;
    const float LN1E4_32 = 9.210340371976184f / 32.0f;

    if (g < 4096) {
        int c = g >> 6, o = g & 63;
        d_const[OFF_QWS + g] = qw[o*128 + 2*c] + qw[o*128 + 2*c + 1];
        d_const[OFF_KWS + g] = kw[o*128 + 2*c] + kw[o*128 + 2*c + 1];
        d_const[OFF_VWS + g] = vw[o*128 + 2*c] + vw[o*128 + 2*c + 1];
    }
    {
        int j = g >> 8, r = g & 255, t4 = r >> 6, o = r & 63;
        int col = (t4 < 2) ? (2*j + t4) : (64 + 2*j + (t4 - 2));
        d_const[OFF_QWPE + g] = qw[o*128 + col];
    }
    if (g < 32) d_const[OFF_FREQ + g] = __expf(-(float)g * LN1E4_32);
    if (g < 64) d_const[OFF_QB + g]   = qb[g];

    const float SW = (float)(2.0 * M_PI / (1.0 + 1e-6));
    int W = g >> 5, j = g & 31;
    int uv = W >> 6, o = W & 63;
    float uu = (float)(uv >> 1), vv = (float)(uv & 1);
    float f = __expf(-(float)j * LN1E4_32);
    float syv, cyv, sxv, cxv;
    __sincosf(uu * SW * f, &syv, &cyv);
    __sincosf(vv * SW * f, &sxv, &cxv);
    float aK = syv*kw[o*128+2*j] + cyv*kw[o*128+2*j+1]
             + sxv*kw[o*128+64+2*j] + cxv*kw[o*128+64+2*j+1];
    float aV = syv*vw[o*128+2*j] + cyv*vw[o*128+2*j+1]
             + sxv*vw[o*128+64+2*j] + cxv*vw[o*128+64+2*j+1];
    #pragma unroll
    for (int s = 16; s > 0; s >>= 1) {
        aK += __shfl_xor_sync(0xffffffffu, aK, s);
        aV += __shfl_xor_sync(0xffffffffu, aV, s);
    }
    if (j == 0) {
        d_const[OFF_KB + W] = aK + kb[o];
        d_const[OFF_VB + W] = aV + vb[o];
    }
}

// ---------------------------------------------------------------------------
// PE-table kernel: g[axis][t][o] = sum_j sin/cos((t/TBL)*PE2*f_j) * qwpe.
// ---------------------------------------------------------------------------
__global__ void __launch_bounds__(64) iw_tab_kernel()
{
    __shared__ float sy[32], cy[32];
    int blk  = blockIdx.x;
    int axis = blk / (TBL+1);
    int t    = blk % (TBL+1);
    int tid  = threadIdx.x;

    const float PE2 = (float)(2.0 * M_PI / (2.0 + 1e-6));
    if (tid < 32) {
        float f = d_const[OFF_FREQ + tid];
        __sincosf(((float)t / (float)TBL) * PE2 * f, &sy[tid], &cy[tid]);
    }
    __syncthreads();

    float acc = 0.f;
    #pragma unroll 4
    for (int j = 0; j < 32; j++) {
        acc = fmaf(sy[j], d_const[OFF_QWPE + j*256 + axis*128 + tid],      acc);
        acc = fmaf(cy[j], d_const[OFF_QWPE + j*256 + axis*128 + 64 + tid], acc);
    }
    pe_tab[(axis*(TBL+1) + t)*64 + tid] = acc;
}

// ---------------------------------------------------------------------------
// Fused kernel: q (lerp + curr matvec) -> attn -> softmax -> value -> out.
// One lane = one pixel. Gather stays R13-shape (direct c-major, chunks of 8).
// Output accumulator explicitly reuses q2's registers. (128,3).
// ---------------------------------------------------------------------------
__global__ void __launch_bounds__(128, 3) iw_fused_kernel(
    const float* __restrict__ supp, const float* __restrict__ curr,
    const float* __restrict__ flow, float* __restrict__ out)
{
    extern __shared__ float sm[];
    for (int i = threadIdx.x; i < 4096; i += 128) {
        sm[FS_QWS + i] = d_const[OFF_QWS + i];
        sm[FS_KWS + i] = d_const[OFF_KWS + i];
        sm[FS_VWS + i] = d_const[OFF_VWS + i];
    }
    for (int i = threadIdx.x; i < 256; i += 128) {
        sm[FS_KB + i] = d_const[OFF_KB + i];
        sm[FS_VB + i] = d_const[OFF_VB + i];
    }
    if (threadIdx.x < 64) sm[FS_QB + threadIdx.x] = d_const[OFF_QB + threadIdx.x];
    __syncthreads();

    const float* s_qws = sm + FS_QWS;
    const float* s_kws = sm + FS_KWS;
    const float* s_vws = sm + FS_VWS;
    const float* s_kb  = sm + FS_KB;
    const float* s_vb  = sm + FS_VB;

    int pix = blockIdx.x * 128 + threadIdx.x;
    int b   = pix >> 16;
    int rem = pix & 65535;
    int yy  = rem >> 8;
    int xx  = rem & 255;

    float2 fl = reinterpret_cast<const float2*>(flow)[pix];
    float gy = (float)yy + fl.y;
    float gx = (float)xx + fl.x;
    float fy = floorf(gy), fx = floorf(gx);
    float dy = gy - fy,    dx = gx - fx;
    int iy = (int)fy, ix = (int)fx;
    int r0 = min(max(iy,     0), HH-1);
    int r1 = min(max(iy + 1, 0), HH-1);
    int c0 = min(max(ix,     0), WW-1);
    int c1 = min(max(ix + 1, 0), WW-1);
    int o00 = r0*WW + c0, o01 = r0*WW + c1;
    int o10 = r1*WW + c0, o11 = r1*WW + c1;

    const float* suppB = supp + b*(CH*HWX);
    const float* currB = curr + b*(CH*HWX) + yy*WW + xx;

    // ================= Q phase =================
    u64t q2[32];
    const u64t* qb2 = reinterpret_cast<const u64t*>(sm + FS_QB);
    #pragma unroll
    for (int i = 0; i < 32; i++) q2[i] = qb2[i];

    // PE lerp over precomputed per-axis tables
    #pragma unroll
    for (int axis = 0; axis < 2; axis++) {
        float d  = axis ? dx : dy;
        float td = d * (float)TBL;
        int   it = (int)td;
        float ft = td - (float)it;
        u64t ft2 = pk2(ft, ft), om2 = pk2(1.f - ft, 1.f - ft);
        const ulonglong2* g0 = reinterpret_cast<const ulonglong2*>(
            pe_tab + (axis*(TBL+1) + it)*64);
        #pragma unroll
        for (int i = 0; i < 16; i++) {
            ulonglong2 a = __ldg(g0 + i);
            ulonglong2 c = __ldg(g0 + 16 + i);   // next row (it+1)
            u64t v0 = ffma2(om2, a.x, q2[2*i]);
            u64t v1 = ffma2(om2, a.y, q2[2*i+1]);
            q2[2*i]   = ffma2(ft2, c.x, v0);
            q2[2*i+1] = ffma2(ft2, c.y, v1);
        }
    }

    // folded current-frame matvec, staged 16-wide for MLP
    for (int cb = 0; cb < 64; cb += 16) {
        float fc[16];
        #pragma unroll
        for (int k = 0; k < 16; k++) fc[k] = __ldg(currB + (cb + k)*HWX);
        #pragma unroll
        for (int k = 0; k < 16; k++) {
            u64t fc2 = pk2(fc[k], fc[k]);
            const ulonglong2* wc4 = reinterpret_cast<const ulonglong2*>(s_qws + (cb + k)*64);
            #pragma unroll
            for (int i = 0; i < 16; i++) {
                ulonglong2 w = wc4[i];
                q2[2*i]   = ffma2(fc2, w.x, q2[2*i]);
                q2[2*i+1] = ffma2(fc2, w.y, q2[2*i+1]);
            }
        }
    }

    // fold softmax scale into q
    {
        const float SC = 0.35355339059327376f;
        u64t sc2 = pk2(SC, SC);
        #pragma unroll
        for (int i = 0; i < 32; i++) q2[i] = fmul2(q2[i], sc2);
    }

    // ================= attn phase =================
    u64t A01[8], A23[8];
    #pragma unroll
    for (int h = 0; h < 8; h++) {
        float av[4];
        #pragma unroll
        for (int u = 0; u < 4; u++) {
            const ulonglong2* kb4 = reinterpret_cast<const ulonglong2*>(s_kb + u*64);
            ulonglong2 wa = kb4[h*2], wb = kb4[h*2 + 1];
            u64t d2 = fmul2(q2[h*4], wa.x);
            d2 = ffma2(q2[h*4+1], wa.y, d2);
            d2 = ffma2(q2[h*4+2], wb.x, d2);
            d2 = ffma2(q2[h*4+3], wb.y, d2);
            float lo, hi; upk2(lo, hi, d2);
            av[u] = lo + hi;
        }
        A01[h] = pk2(av[0], av[1]);
        A23[h] = pk2(av[2], av[3]);
    }

    for (int ch = 0; ch < 8; ch++) {
        float f00[8], f01[8], f10[8], f11[8];
        #pragma unroll
        for (int cc = 0; cc < 8; cc++) {
            const float* p = suppB + (ch*8 + cc)*HWX;
            f00[cc] = __ldg(p + o00);
            f01[cc] = __ldg(p + o01);
            f10[cc] = __ldg(p + o10);
            f11[cc] = __ldg(p + o11);
        }
        #pragma unroll
        for (int cc = 0; cc < 8; cc++) {
            const ulonglong2* wc4 = reinterpret_cast<const ulonglong2*>(s_kws + (ch*8 + cc)*64);
            u64t F01 = pk2(f00[cc], f01[cc]);
            u64t F23 = pk2(f10[cc], f11[cc]);
            #pragma unroll
            for (int h = 0; h < 8; h++) {
                ulonglong2 wa = wc4[h*2], wb = wc4[h*2 + 1];
                u64t d2 = fmul2(q2[h*4], wa.x);
                d2 = ffma2(q2[h*4+1], wa.y, d2);
                d2 = ffma2(q2[h*4+2], wb.x, d2);
                d2 = ffma2(q2[h*4+3], wb.y, d2);
                float lo, hi; upk2(lo, hi, d2);
                float qk = lo + hi;
                u64t qk2 = pk2(qk, qk);
                A01[h] = ffma2(qk2, F01, A01[h]);
                A23[h] = ffma2(qk2, F23, A23[h]);
            }
        }
    }

    // softmax over 4 window positions (SC pre-folded into q)
    #pragma unroll
    for (int h = 0; h < 8; h++) {
        float a0, a1, a2, a3;
        upk2(a0, a1, A01[h]);
        upk2(a2, a3, A23[h]);
        float m = fmaxf(fmaxf(a0, a1), fmaxf(a2, a3));
        float p0 = __expf(a0 - m);
        float p1 = __expf(a1 - m);
        float p2 = __expf(a2 - m);
        float p3 = __expf(a3 - m);
        float inv = __fdividef(1.0f, p0 + p1 + p2 + p3);
        A01[h] = pk2(p0*inv, p1*inv);
        A23[h] = pk2(p2*inv, p3*inv);
    }

    // ================= value phase (q2 reused as output accumulator) ========
    #pragma unroll
    for (int i = 0; i < 32; i++) q2[i] = 0ULL;

    for (int ch = 0; ch < 8; ch++) {
        float f00[8], f01[8], f10[8], f11[8];
        #pragma unroll
        for (int cc = 0; cc < 8; cc++) {
            const float* p = suppB + (ch*8 + cc)*HWX;
            f00[cc] = __ldg(p + o00);
            f01[cc] = __ldg(p + o01);
            f10[cc] = __ldg(p + o10);
            f11[cc] = __ldg(p + o11);
        }
        #pragma unroll
        for (int cc = 0; cc < 8; cc++) {
            const ulonglong2* wc4 = reinterpret_cast<const ulonglong2*>(s_vws + (ch*8 + cc)*64);
            u64t F01 = pk2(f00[cc], f01[cc]);
            u64t F23 = pk2(f10[cc], f11[cc]);
            u64t gv2[8];
            #pragma unroll
            for (int h = 0; h < 8; h++) {
                u64t g2 = fmul2(A01[h], F01);
                g2 = ffma2(A23[h], F23, g2);
                float lo, hi; upk2(lo, hi, g2);
                float gv = lo + hi;
                gv2[h] = pk2(gv, gv);
            }
            #pragma unroll
            for (int i = 0; i < 16; i++) {
                ulonglong2 w = wc4[i];
                q2[2*i]   = ffma2(gv2[i >> 1], w.x, q2[2*i]);
                q2[2*i+1] = ffma2(gv2[i >> 1], w.y, q2[2*i+1]);
            }
        }
    }

    // v pe-bias term (packed) + store
    const u64t* vb2 = reinterpret_cast<const u64t*>(s_vb);
    #pragma unroll
    for (int h = 0; h < 8; h++) {
        float a0, a1, a2, a3;
        upk2(a0, a1, A01[h]);
        upk2(a2, a3, A23[h]);
        u64t b0 = pk2(a0, a0), b1 = pk2(a1, a1);
        u64t b2 = pk2(a2, a2), b3 = pk2(a3, a3);
        #pragma unroll
        for (int k = 0; k < 4; k++) {
            int i = h*4 + k;
            u64t acc = q2[i];
            acc = ffma2(b0, vb2[0*32 + i], acc);
            acc = ffma2(b1, vb2[1*32 + i], acc);
            acc = ffma2(b2, vb2[2*32 + i], acc);
            acc = ffma2(b3, vb2[3*32 + i], acc);
            q2[i] = acc;
        }
    }

    float* outB = out + b*(CH*HWX) + yy*WW + xx;
    #pragma unroll
    for (int i = 0; i < 32; i++) {
        float lo, hi; upk2(lo, hi, q2[i]);
        outB[(2*i)*HWX]     = lo;
        outB[(2*i + 1)*HWX] = hi;
    }
}

// ---------------------------------------------------------------------------
extern "C" void kernel_launch(void* const* d_in, const int* in_sizes, int n_in,
                              void* d_out, int out_size)
{
    const float* supp = (const float*)d_in[0];
    const float* flow = (const float*)d_in[1];
    const float* curr = (const float*)d_in[2];
    const float* qw   = (const float*)d_in[3];
    const float* qb   = (const float*)d_in[4];
    const float* kw   = (const float*)d_in[5];
    const float* kb   = (const float*)d_in[6];
    const float* vw   = (const float*)d_in[7];
    const float* vb   = (const float*)d_in[8];
    float* outp = (float*)d_out;

    cudaFuncSetAttribute(iw_fused_kernel,
                         cudaFuncAttributeMaxDynamicSharedMemorySize, FS_N * 4);

    iw_setup_kernel<<<32, 256>>>(qw, qb, kw, kb, vw, vb);
    iw_tab_kernel<<<2*(TBL+1), 64>>>();
    iw_fused_kernel<<<NPIX / 128, 128, FS_N * 4>>>(supp, curr, flow, outp);
}